// round 2
// baseline (speedup 1.0000x reference)
#include <cuda_runtime.h>
#include <cuda_bf16.h>

// NonMaximaSuppression3d: x (B=4, C=2, D=64, H=256, W=256) fp32.
// out = x where x > max(26 edge-clamped neighbors) else 0.
//
// Decomposition per plane d:
//   r(y,x)  = max(v[x-1], v[x], v[x+1])                 (x clamped)
//   mf(d)   = max(r(y-1), r(y), r(y+1))                 (full 3x3, y clamped)
//   mc(d)   = max(r(y-1), r(y+1), max(v[x-1],v[x+1]))   (8 in-plane nbrs, no center)
//   max_nc  = max(mf(d-1), mc(d), mf(d+1))              (d clamped)
// Edge-pad semantics == clamped indexing (boundary voxels self-compare -> suppressed).
//
// Halo exchange: lanes of a warp cover 32 consecutive float4 segments of one
// row, so L/R halo values come from neighbor lanes via __shfl; only lane 0 /
// lane 31 need a (predicated, single-lane) scalar load or an edge clamp.
// This keeps L1tex wavefronts/step at ~18 instead of ~36.

#define D_DIM 64
#define H_DIM 256
#define W_DIM 256
#define HW    (H_DIM * W_DIM)
#define W4    (W_DIM / 4)
#define FULL  0xffffffffu

__device__ __forceinline__ void row_halo(const float* __restrict__ row,
                                         int x4, int lane, float4 v,
                                         float& L, float& R)
{
    float Lsh = __shfl_up_sync(FULL,   v.w, 1);
    float Rsh = __shfl_down_sync(FULL, v.x, 1);
    if (lane == 0)
        L = (x4 == 0) ? v.x : row[4 * x4 - 1];
    else
        L = Lsh;
    if (lane == 31)
        R = (x4 == W4 - 1) ? v.w : row[4 * x4 + 4];
    else
        R = Rsh;
}

__device__ __forceinline__ void plane_stats(const float* __restrict__ pbase,
                                            int ym, int y, int yp,
                                            int x4, int lane,
                                            float4& xc, float4& mc, float4& mf)
{
    const float* __restrict__ r0 = pbase + ym * W_DIM;
    const float* __restrict__ r1 = pbase + y  * W_DIM;
    const float* __restrict__ r2 = pbase + yp * W_DIM;

    float4 v0 = *((const float4*)r0 + x4);
    float4 v1 = *((const float4*)r1 + x4);
    float4 v2 = *((const float4*)r2 + x4);

    float L0, R0, L1, R1, L2, R2;
    row_halo(r0, x4, lane, v0, L0, R0);
    row_halo(r1, x4, lane, v1, L1, R1);
    row_halo(r2, x4, lane, v2, L2, R2);

    float4 ra, rb, rc, lr;
    // row maxes (include center column)
    ra.x = fmaxf(fmaxf(L0,   v0.x), v0.y);
    ra.y = fmaxf(fmaxf(v0.x, v0.y), v0.z);
    ra.z = fmaxf(fmaxf(v0.y, v0.z), v0.w);
    ra.w = fmaxf(fmaxf(v0.z, v0.w), R0);

    rb.x = fmaxf(fmaxf(L1,   v1.x), v1.y);
    rb.y = fmaxf(fmaxf(v1.x, v1.y), v1.z);
    rb.z = fmaxf(fmaxf(v1.y, v1.z), v1.w);
    rb.w = fmaxf(fmaxf(v1.z, v1.w), R1);

    rc.x = fmaxf(fmaxf(L2,   v2.x), v2.y);
    rc.y = fmaxf(fmaxf(v2.x, v2.y), v2.z);
    rc.z = fmaxf(fmaxf(v2.y, v2.z), v2.w);
    rc.w = fmaxf(fmaxf(v2.z, v2.w), R2);

    // left/right neighbors of center row (exclude center)
    lr.x = fmaxf(L1,   v1.y);
    lr.y = fmaxf(v1.x, v1.z);
    lr.z = fmaxf(v1.y, v1.w);
    lr.w = fmaxf(v1.z, R1);

    mf.x = fmaxf(fmaxf(ra.x, rb.x), rc.x);
    mf.y = fmaxf(fmaxf(ra.y, rb.y), rc.y);
    mf.z = fmaxf(fmaxf(ra.z, rb.z), rc.z);
    mf.w = fmaxf(fmaxf(ra.w, rb.w), rc.w);

    mc.x = fmaxf(fmaxf(ra.x, rc.x), lr.x);
    mc.y = fmaxf(fmaxf(ra.y, rc.y), lr.y);
    mc.z = fmaxf(fmaxf(ra.z, rc.z), lr.z);
    mc.w = fmaxf(fmaxf(ra.w, rc.w), lr.w);

    xc = v1;
}

__global__ __launch_bounds__(256)
void nms3d_kernel(const float* __restrict__ in, float* __restrict__ out)
{
    const int tid  = blockIdx.x * blockDim.x + threadIdx.x;
    const int lane = threadIdx.x & 31;

    const int x4 = tid & (W4 - 1);
    const int y  = (tid / W4) & (H_DIM - 1);
    const int bc = tid / (W4 * H_DIM);

    const float* __restrict__ base  = in  + (size_t)bc * D_DIM * HW;
    float*       __restrict__ obase = out + (size_t)bc * D_DIM * HW;

    const int ym = (y > 0)         ? y - 1 : 0;
    const int yp = (y < H_DIM - 1) ? y + 1 : H_DIM - 1;

    float4 xc, mc, mf, mf_prev;
    plane_stats(base, ym, y, yp, x4, lane, xc, mc, mf);   // plane d=0
    mf_prev = mf;                                         // d-1 clamps to plane 0

    #pragma unroll 1
    for (int d = 0; d < D_DIM; ++d) {
        float4 xcn, mcn, mfn;
        if (d < D_DIM - 1) {
            plane_stats(base + (size_t)(d + 1) * HW, ym, y, yp, x4, lane,
                        xcn, mcn, mfn);
        } else {
            mfn = mf;   // d+1 clamps to last plane
            xcn = xc;
            mcn = mc;
        }

        float4 m, o;
        m.x = fmaxf(fmaxf(mf_prev.x, mc.x), mfn.x);
        m.y = fmaxf(fmaxf(mf_prev.y, mc.y), mfn.y);
        m.z = fmaxf(fmaxf(mf_prev.z, mc.z), mfn.z);
        m.w = fmaxf(fmaxf(mf_prev.w, mc.w), mfn.w);

        o.x = (xc.x > m.x) ? xc.x : 0.0f;
        o.y = (xc.y > m.y) ? xc.y : 0.0f;
        o.z = (xc.z > m.z) ? xc.z : 0.0f;
        o.w = (xc.w > m.w) ? xc.w : 0.0f;

        *((float4*)(obase + (size_t)d * HW + y * W_DIM) + x4) = o;

        mf_prev = mf;
        xc = xcn; mc = mcn; mf = mfn;
    }
}

extern "C" void kernel_launch(void* const* d_in, const int* in_sizes, int n_in,
                              void* d_out, int out_size)
{
    const float* x   = (const float*)d_in[0];
    float*       out = (float*)d_out;

    const int n  = in_sizes[0];
    const int bc = n / (D_DIM * HW);          // = 8 for the reference shape

    const int total   = bc * H_DIM * W4;      // one thread per 4-wide x segment
    const int threads = 256;
    const int blocks  = total / threads;      // total is always a multiple of 256

    nms3d_kernel<<<blocks, threads>>>(x, out);
}